// round 6
// baseline (speedup 1.0000x reference)
#include <cuda_runtime.h>
#include <float.h>

// _VQ_29609504538631 : fused VQ-VAE bottleneck (precision-hardened argmax)
// R3: grid 256x256 -> 512x128 (single co-resident wave, kill wave quantization).
// Math is byte-identical to the rel_err=0.0 R2 kernel.

namespace {
constexpr int Bb = 8;
constexpr int Cc = 1024;
constexpr int Tt = 8192;
constexpr int Kk = 1024;
constexpr int Dd = 8;
constexpr int TT = 128;   // time positions per block
constexpr int NT = 128;   // threads per block
constexpr int CHUNK = 64; // fp32 accumulation chunk for e
}

__global__ __launch_bounds__(NT) void vq_fused(
    const float* __restrict__ z,
    const float* __restrict__ in_w,    // [D, C]
    const float* __restrict__ in_b,    // [D]
    const float* __restrict__ cb,      // [K, D]
    const float* __restrict__ out_w,   // [C, D]
    const float* __restrict__ out_b,   // [C]
    float* __restrict__ out,           // [B, C, T]
    float* __restrict__ ids_out)       // [B, T] (as float), may be null
{
    __shared__ float buf[Dd * Cc];   // 32 KB, reused: in_w -> codebook -> out_w
    __shared__ float aux[Kk];        // half-norms (phase 2) / out_b (phase 3)
    __shared__ float bias_in[Dd];

    const int tid = threadIdx.x;
    const int b   = blockIdx.x / (Tt / TT);
    const int t   = (blockIdx.x % (Tt / TT)) * TT + tid;

    // ---- Phase 0: stage in_w transposed -> buf[c*8+d]
    for (int i = tid; i < Dd * Cc; i += NT) {
        int d = i & 7, c = i >> 3;
        buf[i] = in_w[d * Cc + c];
    }
    if (tid < Dd) bias_in[tid] = in_b[tid];
    __syncthreads();

    // ---- Phase 1: e[d] = sum_c in_w[d][c] * z[b][c][t]
    // fp32 within 64-chunks, chunk sums merged in fp64 (near-exact reduction).
    double e_d[Dd];
    #pragma unroll
    for (int d = 0; d < Dd; d++) e_d[d] = 0.0;

    const float* zp = z + (size_t)b * Cc * Tt + t;
    for (int c0 = 0; c0 < Cc; c0 += CHUNK) {
        float acc[Dd];
        #pragma unroll
        for (int d = 0; d < Dd; d++) acc[d] = 0.0f;
        #pragma unroll 8
        for (int cc = 0; cc < CHUNK; cc++) {
            int c = c0 + cc;
            float v = __ldg(zp + (size_t)c * Tt);
            const float4* w4 = reinterpret_cast<const float4*>(buf + c * 8);
            float4 w0 = w4[0];
            float4 w1 = w4[1];
            acc[0] = fmaf(v, w0.x, acc[0]);
            acc[1] = fmaf(v, w0.y, acc[1]);
            acc[2] = fmaf(v, w0.z, acc[2]);
            acc[3] = fmaf(v, w0.w, acc[3]);
            acc[4] = fmaf(v, w1.x, acc[4]);
            acc[5] = fmaf(v, w1.y, acc[5]);
            acc[6] = fmaf(v, w1.z, acc[6]);
            acc[7] = fmaf(v, w1.w, acc[7]);
        }
        #pragma unroll
        for (int d = 0; d < Dd; d++) e_d[d] += (double)acc[d];
    }
    // round to fp32 (reference's enc is fp32); bias added in fp64 first
    float e32[Dd];
    #pragma unroll
    for (int d = 0; d < Dd; d++) e32[d] = (float)(e_d[d] + (double)bias_in[d]);
    __syncthreads();  // done reading buf (in_w)

    // ---- Phase 2a: stage codebook + half-norms (norms in fp64, rounded once)
    for (int k = tid; k < Kk; k += NT) {
        float4 c0 = __ldg(reinterpret_cast<const float4*>(cb + k * 8));
        float4 c1 = __ldg(reinterpret_cast<const float4*>(cb + k * 8) + 1);
        reinterpret_cast<float4*>(buf)[k * 2]     = c0;
        reinterpret_cast<float4*>(buf)[k * 2 + 1] = c1;
        double n = (double)c0.x*c0.x + (double)c0.y*c0.y
                 + (double)c0.z*c0.z + (double)c0.w*c0.w
                 + (double)c1.x*c1.x + (double)c1.y*c1.y
                 + (double)c1.z*c1.z + (double)c1.w*c1.w;
        aux[k] = (float)(0.5 * n);
    }
    __syncthreads();

    // ---- Phase 2b: argmin_k dist == argmax_k (e.cb[k] - 0.5||cb[k]||^2)
    // fp32 scan keeps top-2; fp64 rescore resolves near-ties exactly.
    float best1 = -FLT_MAX, best2 = -FLT_MAX;
    int   bi1 = 0, bi2 = 0;
    #pragma unroll 4
    for (int k = 0; k < Kk; k++) {
        const float4* c4 = reinterpret_cast<const float4*>(buf + k * 8);
        float4 c0 = c4[0];
        float4 c1 = c4[1];
        float dot;
        dot = fmaf(e32[0], c0.x, 0.0f);
        dot = fmaf(e32[1], c0.y, dot);
        dot = fmaf(e32[2], c0.z, dot);
        dot = fmaf(e32[3], c0.w, dot);
        dot = fmaf(e32[4], c1.x, dot);
        dot = fmaf(e32[5], c1.y, dot);
        dot = fmaf(e32[6], c1.z, dot);
        dot = fmaf(e32[7], c1.w, dot);
        float s = dot - aux[k];
        if (s > best1) {
            best2 = best1; bi2 = bi1;
            best1 = s;     bi1 = k;
        } else if (s > best2) {
            best2 = s;     bi2 = k;
        }
    }

    // fp64 refine of the two candidates (exact ordering on fp32 e)
    {
        double s_c[2];
        int    k_c[2] = {bi1, bi2};
        #pragma unroll
        for (int j = 0; j < 2; j++) {
            const float* w = buf + k_c[j] * 8;
            double dot = 0.0, nrm = 0.0;
            #pragma unroll
            for (int i = 0; i < Dd; i++) {
                double wi = (double)w[i];
                dot += (double)e32[i] * wi;
                nrm += wi * wi;
            }
            s_c[j] = dot - 0.5 * nrm;
        }
        if (s_c[1] > s_c[0] || (s_c[1] == s_c[0] && bi2 < bi1)) bi1 = bi2;
    }
    const int bi = bi1;

    // grab winning code before buf is overwritten
    float q[Dd];
    {
        const float4* c4 = reinterpret_cast<const float4*>(buf + bi * 8);
        float4 c0 = c4[0];
        float4 c1 = c4[1];
        q[0]=c0.x; q[1]=c0.y; q[2]=c0.z; q[3]=c0.w;
        q[4]=c1.x; q[5]=c1.y; q[6]=c1.z; q[7]=c1.w;
    }
    __syncthreads();  // done reading buf (codebook)

    // ---- Phase 3a: stage out_w ([C,D] layout already c*8+d) and out_b
    for (int i = tid; i < Cc * Dd; i += NT) buf[i] = out_w[i];
    for (int i = tid; i < Cc; i += NT)      aux[i] = out_b[i];
    __syncthreads();

    // ---- Phase 3b: out[b][c][t] = q . out_w[c,:] + out_b[c]
    float* op = out + (size_t)b * Cc * Tt + t;
    #pragma unroll 8
    for (int c = 0; c < Cc; c++) {
        const float4* w4 = reinterpret_cast<const float4*>(buf + c * 8);
        float4 w0 = w4[0];
        float4 w1 = w4[1];
        float s;
        s = fmaf(q[0], w0.x, 0.0f);
        s = fmaf(q[1], w0.y, s);
        s = fmaf(q[2], w0.z, s);
        s = fmaf(q[3], w0.w, s);
        s = fmaf(q[4], w1.x, s);
        s = fmaf(q[5], w1.y, s);
        s = fmaf(q[6], w1.z, s);
        s = fmaf(q[7], w1.w, s);
        op[(size_t)c * Tt] = s + aux[c];
    }

    if (ids_out) ids_out[(size_t)b * Tt + t] = (float)bi;
}

extern "C" void kernel_launch(void* const* d_in, const int* in_sizes, int n_in,
                              void* d_out, int out_size) {
    const float* z     = (const float*)d_in[0];
    const float* in_w  = (const float*)d_in[1];
    const float* in_b  = (const float*)d_in[2];
    const float* cb    = (const float*)d_in[3];
    const float* out_w = (const float*)d_in[4];
    const float* out_b = (const float*)d_in[5];

    float* out = (float*)d_out;
    const long long out_elems = (long long)Bb * Cc * Tt;
    float* ids = (out_size > out_elems) ? out + out_elems : nullptr;

    dim3 grid(Bb * (Tt / TT));   // 512 blocks of 128 threads — one co-resident wave
    vq_fused<<<grid, NT>>>(z, in_w, in_b, cb, out_w, out_b, out, ids);
}

// round 7
// speedup vs baseline: 1.0018x; 1.0018x over previous
#include <cuda_runtime.h>
#include <float.h>

// _VQ_29609504538631 : fused VQ-VAE bottleneck (precision-hardened argmax)
// R3: grid 256x256 -> 512x128 (single co-resident wave, kill wave quantization).
// Math is byte-identical to the rel_err=0.0 R2 kernel.

namespace {
constexpr int Bb = 8;
constexpr int Cc = 1024;
constexpr int Tt = 8192;
constexpr int Kk = 1024;
constexpr int Dd = 8;
constexpr int TT = 128;   // time positions per block
constexpr int NT = 128;   // threads per block
constexpr int CHUNK = 64; // fp32 accumulation chunk for e
}

__global__ __launch_bounds__(NT) void vq_fused(
    const float* __restrict__ z,
    const float* __restrict__ in_w,    // [D, C]
    const float* __restrict__ in_b,    // [D]
    const float* __restrict__ cb,      // [K, D]
    const float* __restrict__ out_w,   // [C, D]
    const float* __restrict__ out_b,   // [C]
    float* __restrict__ out,           // [B, C, T]
    float* __restrict__ ids_out)       // [B, T] (as float), may be null
{
    __shared__ float buf[Dd * Cc];   // 32 KB, reused: in_w -> codebook -> out_w
    __shared__ float aux[Kk];        // half-norms (phase 2) / out_b (phase 3)
    __shared__ float bias_in[Dd];

    const int tid = threadIdx.x;
    const int b   = blockIdx.x / (Tt / TT);
    const int t   = (blockIdx.x % (Tt / TT)) * TT + tid;

    // ---- Phase 0: stage in_w transposed -> buf[c*8+d]
    for (int i = tid; i < Dd * Cc; i += NT) {
        int d = i & 7, c = i >> 3;
        buf[i] = in_w[d * Cc + c];
    }
    if (tid < Dd) bias_in[tid] = in_b[tid];
    __syncthreads();

    // ---- Phase 1: e[d] = sum_c in_w[d][c] * z[b][c][t]
    // fp32 within 64-chunks, chunk sums merged in fp64 (near-exact reduction).
    double e_d[Dd];
    #pragma unroll
    for (int d = 0; d < Dd; d++) e_d[d] = 0.0;

    const float* zp = z + (size_t)b * Cc * Tt + t;
    for (int c0 = 0; c0 < Cc; c0 += CHUNK) {
        float acc[Dd];
        #pragma unroll
        for (int d = 0; d < Dd; d++) acc[d] = 0.0f;
        #pragma unroll 8
        for (int cc = 0; cc < CHUNK; cc++) {
            int c = c0 + cc;
            float v = __ldg(zp + (size_t)c * Tt);
            const float4* w4 = reinterpret_cast<const float4*>(buf + c * 8);
            float4 w0 = w4[0];
            float4 w1 = w4[1];
            acc[0] = fmaf(v, w0.x, acc[0]);
            acc[1] = fmaf(v, w0.y, acc[1]);
            acc[2] = fmaf(v, w0.z, acc[2]);
            acc[3] = fmaf(v, w0.w, acc[3]);
            acc[4] = fmaf(v, w1.x, acc[4]);
            acc[5] = fmaf(v, w1.y, acc[5]);
            acc[6] = fmaf(v, w1.z, acc[6]);
            acc[7] = fmaf(v, w1.w, acc[7]);
        }
        #pragma unroll
        for (int d = 0; d < Dd; d++) e_d[d] += (double)acc[d];
    }
    // round to fp32 (reference's enc is fp32); bias added in fp64 first
    float e32[Dd];
    #pragma unroll
    for (int d = 0; d < Dd; d++) e32[d] = (float)(e_d[d] + (double)bias_in[d]);
    __syncthreads();  // done reading buf (in_w)

    // ---- Phase 2a: stage codebook + half-norms (norms in fp64, rounded once)
    for (int k = tid; k < Kk; k += NT) {
        float4 c0 = __ldg(reinterpret_cast<const float4*>(cb + k * 8));
        float4 c1 = __ldg(reinterpret_cast<const float4*>(cb + k * 8) + 1);
        reinterpret_cast<float4*>(buf)[k * 2]     = c0;
        reinterpret_cast<float4*>(buf)[k * 2 + 1] = c1;
        double n = (double)c0.x*c0.x + (double)c0.y*c0.y
                 + (double)c0.z*c0.z + (double)c0.w*c0.w
                 + (double)c1.x*c1.x + (double)c1.y*c1.y
                 + (double)c1.z*c1.z + (double)c1.w*c1.w;
        aux[k] = (float)(0.5 * n);
    }
    __syncthreads();

    // ---- Phase 2b: argmin_k dist == argmax_k (e.cb[k] - 0.5||cb[k]||^2)
    // fp32 scan keeps top-2; fp64 rescore resolves near-ties exactly.
    float best1 = -FLT_MAX, best2 = -FLT_MAX;
    int   bi1 = 0, bi2 = 0;
    #pragma unroll 4
    for (int k = 0; k < Kk; k++) {
        const float4* c4 = reinterpret_cast<const float4*>(buf + k * 8);
        float4 c0 = c4[0];
        float4 c1 = c4[1];
        float dot;
        dot = fmaf(e32[0], c0.x, 0.0f);
        dot = fmaf(e32[1], c0.y, dot);
        dot = fmaf(e32[2], c0.z, dot);
        dot = fmaf(e32[3], c0.w, dot);
        dot = fmaf(e32[4], c1.x, dot);
        dot = fmaf(e32[5], c1.y, dot);
        dot = fmaf(e32[6], c1.z, dot);
        dot = fmaf(e32[7], c1.w, dot);
        float s = dot - aux[k];
        if (s > best1) {
            best2 = best1; bi2 = bi1;
            best1 = s;     bi1 = k;
        } else if (s > best2) {
            best2 = s;     bi2 = k;
        }
    }

    // fp64 refine of the two candidates (exact ordering on fp32 e)
    {
        double s_c[2];
        int    k_c[2] = {bi1, bi2};
        #pragma unroll
        for (int j = 0; j < 2; j++) {
            const float* w = buf + k_c[j] * 8;
            double dot = 0.0, nrm = 0.0;
            #pragma unroll
            for (int i = 0; i < Dd; i++) {
                double wi = (double)w[i];
                dot += (double)e32[i] * wi;
                nrm += wi * wi;
            }
            s_c[j] = dot - 0.5 * nrm;
        }
        if (s_c[1] > s_c[0] || (s_c[1] == s_c[0] && bi2 < bi1)) bi1 = bi2;
    }
    const int bi = bi1;

    // grab winning code before buf is overwritten
    float q[Dd];
    {
        const float4* c4 = reinterpret_cast<const float4*>(buf + bi * 8);
        float4 c0 = c4[0];
        float4 c1 = c4[1];
        q[0]=c0.x; q[1]=c0.y; q[2]=c0.z; q[3]=c0.w;
        q[4]=c1.x; q[5]=c1.y; q[6]=c1.z; q[7]=c1.w;
    }
    __syncthreads();  // done reading buf (codebook)

    // ---- Phase 3a: stage out_w ([C,D] layout already c*8+d) and out_b
    for (int i = tid; i < Cc * Dd; i += NT) buf[i] = out_w[i];
    for (int i = tid; i < Cc; i += NT)      aux[i] = out_b[i];
    __syncthreads();

    // ---- Phase 3b: out[b][c][t] = q . out_w[c,:] + out_b[c]
    float* op = out + (size_t)b * Cc * Tt + t;
    #pragma unroll 8
    for (int c = 0; c < Cc; c++) {
        const float4* w4 = reinterpret_cast<const float4*>(buf + c * 8);
        float4 w0 = w4[0];
        float4 w1 = w4[1];
        float s;
        s = fmaf(q[0], w0.x, 0.0f);
        s = fmaf(q[1], w0.y, s);
        s = fmaf(q[2], w0.z, s);
        s = fmaf(q[3], w0.w, s);
        s = fmaf(q[4], w1.x, s);
        s = fmaf(q[5], w1.y, s);
        s = fmaf(q[6], w1.z, s);
        s = fmaf(q[7], w1.w, s);
        op[(size_t)c * Tt] = s + aux[c];
    }

    if (ids_out) ids_out[(size_t)b * Tt + t] = (float)bi;
}

extern "C" void kernel_launch(void* const* d_in, const int* in_sizes, int n_in,
                              void* d_out, int out_size) {
    const float* z     = (const float*)d_in[0];
    const float* in_w  = (const float*)d_in[1];
    const float* in_b  = (const float*)d_in[2];
    const float* cb    = (const float*)d_in[3];
    const float* out_w = (const float*)d_in[4];
    const float* out_b = (const float*)d_in[5];

    float* out = (float*)d_out;
    const long long out_elems = (long long)Bb * Cc * Tt;
    float* ids = (out_size > out_elems) ? out + out_elems : nullptr;

    dim3 grid(Bb * (Tt / TT));   // 512 blocks of 128 threads — one co-resident wave
    vq_fused<<<grid, NT>>>(z, in_w, in_b, cb, out_w, out_b, out, ids);
}

// round 8
// speedup vs baseline: 1.0592x; 1.0573x over previous
#include <cuda_runtime.h>
#include <float.h>

// _VQ_29609504538631 : fused VQ-VAE bottleneck
// R7: 2-way token slicing. Each token is processed by a thread PAIR:
//   slice s sums channels [512s,512s+512) in phase 1, scans codes
//   [512s,512s+512) in phase 2, writes channels [512s,512s+512) in phase 3.
// Doubles resident warps (13.8 -> ~28 per SM) to cover LDS/LDG latency.
// Argmax robustness: fp64 rescore of ALL 4 slice candidates (>= R2 rigor).

namespace {
constexpr int Bb = 8;
constexpr int Cc = 1024;
constexpr int Tt = 8192;
constexpr int Kk = 1024;
constexpr int Dd = 8;
constexpr int TT  = 128;   // tokens per block
constexpr int SL  = 2;     // slices per token
constexpr int NT  = TT * SL;          // 256 threads
constexpr int CH  = Cc / SL;          // 512 channels per slice
constexpr int KH  = Kk / SL;          // 512 codes per slice
constexpr int CHUNK = 64;             // fp32 accumulation chunk
}

__global__ __launch_bounds__(NT, 4) void vq_fused(
    const float* __restrict__ z,
    const float* __restrict__ in_w,    // [D, C]
    const float* __restrict__ in_b,    // [D]
    const float* __restrict__ cb,      // [K, D]
    const float* __restrict__ out_w,   // [C, D]
    const float* __restrict__ out_b,   // [C]
    float* __restrict__ out,           // [B, C, T]
    float* __restrict__ ids_out)       // [B, T] (as float), may be null
{
    __shared__ float  buf[Dd * Cc];        // 32 KB: in_w -> codebook -> out_w
    __shared__ float  aux[Kk];             // half-norms / out_b
    __shared__ double exch[SL][TT][Dd];    // 16 KB: phase-1 fp64 partials
    __shared__ float  cand_s[SL][TT][2];   // phase-2 candidate scores
    __shared__ int    cand_i[SL][TT][2];   // phase-2 candidate indices
    __shared__ float  bias_in[Dd];

    const int tid   = threadIdx.x;
    const int slice = tid >> 7;            // 0 or 1 (warps 0-3 vs 4-7)
    const int lt    = tid & (TT - 1);      // token within block
    const int b     = blockIdx.x / (Tt / TT);
    const int t     = (blockIdx.x % (Tt / TT)) * TT + lt;

    // ---- Phase 0: stage in_w transposed -> buf[c*8+d]
    for (int i = tid; i < Dd * Cc; i += NT) {
        int d = i & 7, c = i >> 3;
        buf[i] = in_w[d * Cc + c];
    }
    if (tid < Dd) bias_in[tid] = in_b[tid];
    __syncthreads();

    // ---- Phase 1: partial e over this slice's 512 channels
    // fp32 within 64-chunks, chunk sums merged in fp64.
    double part[Dd];
    #pragma unroll
    for (int d = 0; d < Dd; d++) part[d] = 0.0;

    const float* zp = z + (size_t)b * Cc * Tt + t;
    const int cbeg = slice * CH;
    for (int c0 = cbeg; c0 < cbeg + CH; c0 += CHUNK) {
        float acc[Dd];
        #pragma unroll
        for (int d = 0; d < Dd; d++) acc[d] = 0.0f;
        #pragma unroll 8
        for (int cc = 0; cc < CHUNK; cc++) {
            int c = c0 + cc;
            float v = __ldg(zp + (size_t)c * Tt);
            const float4* w4 = reinterpret_cast<const float4*>(buf + c * 8);
            float4 w0 = w4[0];
            float4 w1 = w4[1];
            acc[0] = fmaf(v, w0.x, acc[0]);
            acc[1] = fmaf(v, w0.y, acc[1]);
            acc[2] = fmaf(v, w0.z, acc[2]);
            acc[3] = fmaf(v, w0.w, acc[3]);
            acc[4] = fmaf(v, w1.x, acc[4]);
            acc[5] = fmaf(v, w1.y, acc[5]);
            acc[6] = fmaf(v, w1.z, acc[6]);
            acc[7] = fmaf(v, w1.w, acc[7]);
        }
        #pragma unroll
        for (int d = 0; d < Dd; d++) part[d] += (double)acc[d];
    }
    #pragma unroll
    for (int d = 0; d < Dd; d++) exch[slice][lt][d] = part[d];
    __syncthreads();   // buf(in_w) reads done; partials published

    // merge partials in identical order on both threads of the pair
    float e32[Dd];
    #pragma unroll
    for (int d = 0; d < Dd; d++) {
        double s = exch[0][lt][d] + exch[1][lt][d];
        e32[d] = (float)(s + (double)bias_in[d]);
    }

    // ---- Phase 2a: stage codebook + half-norms (fp64 norms, rounded once)
    for (int k = tid; k < Kk; k += NT) {
        float4 c0 = __ldg(reinterpret_cast<const float4*>(cb + k * 8));
        float4 c1 = __ldg(reinterpret_cast<const float4*>(cb + k * 8) + 1);
        reinterpret_cast<float4*>(buf)[k * 2]     = c0;
        reinterpret_cast<float4*>(buf)[k * 2 + 1] = c1;
        double n = (double)c0.x*c0.x + (double)c0.y*c0.y
                 + (double)c0.z*c0.z + (double)c0.w*c0.w
                 + (double)c1.x*c1.x + (double)c1.y*c1.y
                 + (double)c1.z*c1.z + (double)c1.w*c1.w;
        aux[k] = (float)(0.5 * n);
    }
    __syncthreads();

    // ---- Phase 2b: scan this slice's 512 codes, keep fp32 top-2
    float best1 = -FLT_MAX, best2 = -FLT_MAX;
    int   bi1 = slice * KH, bi2 = slice * KH;
    const int kbeg = slice * KH;
    #pragma unroll 4
    for (int k = kbeg; k < kbeg + KH; k++) {
        const float4* c4 = reinterpret_cast<const float4*>(buf + k * 8);
        float4 c0 = c4[0];
        float4 c1 = c4[1];
        float dot;
        dot = fmaf(e32[0], c0.x, 0.0f);
        dot = fmaf(e32[1], c0.y, dot);
        dot = fmaf(e32[2], c0.z, dot);
        dot = fmaf(e32[3], c0.w, dot);
        dot = fmaf(e32[4], c1.x, dot);
        dot = fmaf(e32[5], c1.y, dot);
        dot = fmaf(e32[6], c1.z, dot);
        dot = fmaf(e32[7], c1.w, dot);
        float s = dot - aux[k];
        if (s > best1) {
            best2 = best1; bi2 = bi1;
            best1 = s;     bi1 = k;
        } else if (s > best2) {
            best2 = s;     bi2 = k;
        }
    }
    cand_s[slice][lt][0] = best1;  cand_i[slice][lt][0] = bi1;
    cand_s[slice][lt][1] = best2;  cand_i[slice][lt][1] = bi2;
    __syncthreads();

    // ---- fp64 rescore of all 4 candidates; lowest index wins ties.
    // Both threads of the pair compute this identically.
    int bi = 0;
    {
        double bscore = -DBL_MAX;
        int    bidx   = Kk;
        #pragma unroll
        for (int j = 0; j < 4; j++) {
            int kc = cand_i[j >> 1][lt][j & 1];
            const float* w = buf + kc * 8;
            double dot = 0.0, nrm = 0.0;
            #pragma unroll
            for (int i = 0; i < Dd; i++) {
                double wi = (double)w[i];
                dot += (double)e32[i] * wi;
                nrm += wi * wi;
            }
            double sc = dot - 0.5 * nrm;
            if (sc > bscore || (sc == bscore && kc < bidx)) {
                bscore = sc; bidx = kc;
            }
        }
        bi = bidx;
    }

    // grab winning code before buf is overwritten
    float q[Dd];
    {
        const float4* c4 = reinterpret_cast<const float4*>(buf + bi * 8);
        float4 c0 = c4[0];
        float4 c1 = c4[1];
        q[0]=c0.x; q[1]=c0.y; q[2]=c0.z; q[3]=c0.w;
        q[4]=c1.x; q[5]=c1.y; q[6]=c1.z; q[7]=c1.w;
    }
    __syncthreads();   // codebook reads done

    // ---- Phase 3a: stage out_w ([C,D] already c*8+d) and out_b
    for (int i = tid; i < Cc * Dd; i += NT) buf[i] = out_w[i];
    for (int i = tid; i < Cc; i += NT)      aux[i] = out_b[i];
    __syncthreads();

    // ---- Phase 3b: this slice writes channels [cbeg, cbeg+512)
    float* op = out + (size_t)b * Cc * Tt + t;
    #pragma unroll 8
    for (int c = cbeg; c < cbeg + CH; c++) {
        const float4* w4 = reinterpret_cast<const float4*>(buf + c * 8);
        float4 w0 = w4[0];
        float4 w1 = w4[1];
        float s;
        s = fmaf(q[0], w0.x, 0.0f);
        s = fmaf(q[1], w0.y, s);
        s = fmaf(q[2], w0.z, s);
        s = fmaf(q[3], w0.w, s);
        s = fmaf(q[4], w1.x, s);
        s = fmaf(q[5], w1.y, s);
        s = fmaf(q[6], w1.z, s);
        s = fmaf(q[7], w1.w, s);
        op[(size_t)c * Tt] = s + aux[c];
    }

    if (slice == 0 && ids_out) ids_out[(size_t)b * Tt + t] = (float)bi;
}

extern "C" void kernel_launch(void* const* d_in, const int* in_sizes, int n_in,
                              void* d_out, int out_size) {
    const float* z     = (const float*)d_in[0];
    const float* in_w  = (const float*)d_in[1];
    const float* in_b  = (const float*)d_in[2];
    const float* cb    = (const float*)d_in[3];
    const float* out_w = (const float*)d_in[4];
    const float* out_b = (const float*)d_in[5];

    float* out = (float*)d_out;
    const long long out_elems = (long long)Bb * Cc * Tt;
    float* ids = (out_size > out_elems) ? out + out_elems : nullptr;

    dim3 grid(Bb * (Tt / TT));   // 512 blocks x 256 threads, 2 threads/token
    vq_fused<<<grid, NT>>>(z, in_w, in_b, cb, out_w, out_b, out, ids);
}

// round 9
// speedup vs baseline: 1.1874x; 1.1210x over previous
#include <cuda_runtime.h>
#include <float.h>

// _VQ_29609504538631 : fused VQ-VAE bottleneck
// R8: 2 tokens per thread (t even-pair) + f32x2 packed math + branchless top-2.
//   - one LDS.128 weight fetch serves 2 tokens; z via LDG.64; out via STG.64
//   - fma.rn.f32x2 packs d-pairs: each lane = bit-identical scalar FMA chain
//   - phase-2 top-2 tracking is fully predicated (no BSSY/BSYNC divergence)
// Exactness skeleton unchanged: chunk-64 fp32 + fp64 merge for e, fp64 norms,
// per-slice top-2 + fp64 rescore of all 4 candidates per token.

namespace {
constexpr int Bb = 8;
constexpr int Cc = 1024;
constexpr int Tt = 8192;
constexpr int Kk = 1024;
constexpr int Dd = 8;
constexpr int TT  = 256;              // tokens per block (128 pairs)
constexpr int NP  = 128;              // token-pairs per block
constexpr int SL  = 2;                // channel/code slices per token
constexpr int NT  = NP * SL;          // 256 threads
constexpr int CH  = Cc / SL;          // 512 channels per slice
constexpr int KH  = Kk / SL;          // 512 codes per slice
constexpr int CHUNK = 64;             // fp32 accumulation chunk (validated)
}

typedef unsigned long long u64;

__device__ __forceinline__ u64 pk2(float lo, float hi) {
    u64 r; asm("mov.b64 %0, {%1,%2};" : "=l"(r) : "f"(lo), "f"(hi)); return r;
}
__device__ __forceinline__ void upk2(u64 v, float& lo, float& hi) {
    asm("mov.b64 {%0,%1}, %2;" : "=f"(lo), "=f"(hi) : "l"(v));
}
__device__ __forceinline__ u64 ffma2(u64 a, u64 b, u64 c) {
    u64 r; asm("fma.rn.f32x2 %0, %1, %2, %3;" : "=l"(r) : "l"(a), "l"(b), "l"(c)); return r;
}
__device__ __forceinline__ u64 fmul2(u64 a, u64 b) {
    u64 r; asm("mul.rn.f32x2 %0, %1, %2;" : "=l"(r) : "l"(a), "l"(b)); return r;
}

__global__ __launch_bounds__(NT, 2) void vq_fused(
    const float* __restrict__ z,
    const float* __restrict__ in_w,    // [D, C]
    const float* __restrict__ in_b,    // [D]
    const float* __restrict__ cb,      // [K, D]
    const float* __restrict__ out_w,   // [C, D]
    const float* __restrict__ out_b,   // [C]
    float* __restrict__ out,           // [B, C, T]
    float* __restrict__ ids_out)       // [B, T] (as float), may be null
{
    __shared__ __align__(16) float buf[Dd * Cc];    // 32 KB: in_w->cb->out_w
    __shared__ __align__(8)  float aux[Kk];         // half-norms / out_b
    __shared__ double exch[SL][NP][2][Dd];          // 32 KB fp64 partials
    __shared__ int    cand_i[SL][NP][2][2];         // 4 KB candidate ids
    __shared__ float  bias_in[Dd];

    const int tid   = threadIdx.x;
    const int slice = tid >> 7;           // 0/1
    const int pr    = tid & (NP - 1);     // pair index in block
    const int b     = blockIdx.x / (Tt / TT);
    const int t0    = (blockIdx.x % (Tt / TT)) * TT + 2 * pr;   // even

    // ---- Phase 0: stage in_w transposed -> buf[c*8+d]
    for (int i = tid; i < Dd * Cc; i += NT) {
        int d = i & 7, c = i >> 3;
        buf[i] = in_w[d * Cc + c];
    }
    if (tid < Dd) bias_in[tid] = in_b[tid];
    __syncthreads();

    // ---- Phase 1: partial e over this slice's 512 channels, 2 tokens packed.
    // acc lanes = (d even, d odd); splat v per token. Per-lane FMA chain is
    // bit-identical to the scalar validated version.
    double p0[Dd], p1[Dd];
    #pragma unroll
    for (int d = 0; d < Dd; d++) { p0[d] = 0.0; p1[d] = 0.0; }

    const float* zp = z + (size_t)b * Cc * Tt + t0;
    const int cbeg = slice * CH;
    for (int c0 = cbeg; c0 < cbeg + CH; c0 += CHUNK) {
        u64 a0[4], a1[4];
        #pragma unroll
        for (int j = 0; j < 4; j++) { a0[j] = 0ull; a1[j] = 0ull; }
        #pragma unroll 8
        for (int cc = 0; cc < CHUNK; cc++) {
            int c = c0 + cc;
            float2 v2 = __ldg(reinterpret_cast<const float2*>(zp + (size_t)c * Tt));
            u64 v0 = pk2(v2.x, v2.x);
            u64 v1 = pk2(v2.y, v2.y);
            const u64* wp = reinterpret_cast<const u64*>(buf + c * 8);
            u64 w0 = wp[0], w1 = wp[1], w2 = wp[2], w3 = wp[3];
            a0[0] = ffma2(v0, w0, a0[0]);
            a0[1] = ffma2(v0, w1, a0[1]);
            a0[2] = ffma2(v0, w2, a0[2]);
            a0[3] = ffma2(v0, w3, a0[3]);
            a1[0] = ffma2(v1, w0, a1[0]);
            a1[1] = ffma2(v1, w1, a1[1]);
            a1[2] = ffma2(v1, w2, a1[2]);
            a1[3] = ffma2(v1, w3, a1[3]);
        }
        #pragma unroll
        for (int j = 0; j < 4; j++) {
            float lo, hi;
            upk2(a0[j], lo, hi); p0[2*j] += (double)lo; p0[2*j+1] += (double)hi;
            upk2(a1[j], lo, hi); p1[2*j] += (double)lo; p1[2*j+1] += (double)hi;
        }
    }
    #pragma unroll
    for (int d = 0; d < Dd; d++) {
        exch[slice][pr][0][d] = p0[d];
        exch[slice][pr][1][d] = p1[d];
    }
    __syncthreads();   // buf(in_w) reads done; partials published

    // merge partials in identical order on both slice threads
    float e0[Dd], e1[Dd];
    #pragma unroll
    for (int d = 0; d < Dd; d++) {
        e0[d] = (float)((exch[0][pr][0][d] + exch[1][pr][0][d]) + (double)bias_in[d]);
        e1[d] = (float)((exch[0][pr][1][d] + exch[1][pr][1][d]) + (double)bias_in[d]);
    }

    // ---- Phase 2a: stage codebook + fp64 half-norms
    for (int k = tid; k < Kk; k += NT) {
        float4 c0 = __ldg(reinterpret_cast<const float4*>(cb + k * 8));
        float4 c1 = __ldg(reinterpret_cast<const float4*>(cb + k * 8) + 1);
        reinterpret_cast<float4*>(buf)[k * 2]     = c0;
        reinterpret_cast<float4*>(buf)[k * 2 + 1] = c1;
        double n = (double)c0.x*c0.x + (double)c0.y*c0.y
                 + (double)c0.z*c0.z + (double)c0.w*c0.w
                 + (double)c1.x*c1.x + (double)c1.y*c1.y
                 + (double)c1.z*c1.z + (double)c1.w*c1.w;
        aux[k] = (float)(0.5 * n);
    }
    __syncthreads();

    // ---- Phase 2b: scan this slice's 512 codes for both tokens.
    // Packed-over-d dot, branchless top-2 per token.
    u64 ep0[4], ep1[4];
    #pragma unroll
    for (int j = 0; j < 4; j++) {
        ep0[j] = pk2(e0[2*j], e0[2*j+1]);
        ep1[j] = pk2(e1[2*j], e1[2*j+1]);
    }
    float b1t0 = -FLT_MAX, b2t0 = -FLT_MAX, b1t1 = -FLT_MAX, b2t1 = -FLT_MAX;
    int   i1t0 = slice*KH, i2t0 = slice*KH, i1t1 = slice*KH, i2t1 = slice*KH;
    const int kbeg = slice * KH;
    #pragma unroll 2
    for (int k = kbeg; k < kbeg + KH; k++) {
        const u64* wp = reinterpret_cast<const u64*>(buf + k * 8);
        u64 w0 = wp[0], w1 = wp[1], w2 = wp[2], w3 = wp[3];
        float av = aux[k];
        u64 d0 = ffma2(ep0[0], w0, ffma2(ep0[1], w1,
                 ffma2(ep0[2], w2, fmul2(ep0[3], w3))));
        u64 d1 = ffma2(ep1[0], w0, ffma2(ep1[1], w1,
                 ffma2(ep1[2], w2, fmul2(ep1[3], w3))));
        float lo, hi;
        upk2(d0, lo, hi); float s0 = (lo + hi) - av;
        upk2(d1, lo, hi); float s1 = (lo + hi) - av;
        // branchless top-2 (sorting network)
        {
            bool q2 = s0 > b2t0;
            float c2 = q2 ? s0 : b2t0;  int j2 = q2 ? k : i2t0;
            bool q1 = s0 > b1t0;
            b2t0 = q1 ? b1t0 : c2;      i2t0 = q1 ? i1t0 : j2;
            b1t0 = q1 ? s0 : b1t0;      i1t0 = q1 ? k : i1t0;
        }
        {
            bool q2 = s1 > b2t1;
            float c2 = q2 ? s1 : b2t1;  int j2 = q2 ? k : i2t1;
            bool q1 = s1 > b1t1;
            b2t1 = q1 ? b1t1 : c2;      i2t1 = q1 ? i1t1 : j2;
            b1t1 = q1 ? s1 : b1t1;      i1t1 = q1 ? k : i1t1;
        }
    }
    cand_i[slice][pr][0][0] = i1t0;  cand_i[slice][pr][0][1] = i2t0;
    cand_i[slice][pr][1][0] = i1t1;  cand_i[slice][pr][1][1] = i2t1;
    __syncthreads();

    // ---- fp64 rescore of all 4 candidates per token; lowest index on ties.
    int bi0 = 0, bi1 = 0;
    #pragma unroll
    for (int tk = 0; tk < 2; tk++) {
        const float* ee = tk ? e1 : e0;
        double bscore = -DBL_MAX;
        int    bidx   = Kk;
        #pragma unroll
        for (int j = 0; j < 4; j++) {
            int kc = cand_i[j >> 1][pr][tk][j & 1];
            const float* w = buf + kc * 8;
            double dot = 0.0, nrm = 0.0;
            #pragma unroll
            for (int i = 0; i < Dd; i++) {
                double wi = (double)w[i];
                dot += (double)ee[i] * wi;
                nrm += wi * wi;
            }
            double sc = dot - 0.5 * nrm;
            if (sc > bscore || (sc == bscore && kc < bidx)) {
                bscore = sc; bidx = kc;
            }
        }
        if (tk) bi1 = bidx; else bi0 = bidx;
    }

    // grab winning codes (as d-pairs) before buf is overwritten
    u64 q0p[4], q1p[4];
    {
        const u64* w0 = reinterpret_cast<const u64*>(buf + bi0 * 8);
        const u64* w1 = reinterpret_cast<const u64*>(buf + bi1 * 8);
        #pragma unroll
        for (int j = 0; j < 4; j++) { q0p[j] = w0[j]; q1p[j] = w1[j]; }
    }
    __syncthreads();   // codebook reads done

    // ---- Phase 3a: stage out_w ([C,D] already c*8+d) and out_b
    for (int i = tid; i < Cc * Dd; i += NT) buf[i] = out_w[i];
    for (int i = tid; i < Cc; i += NT)      aux[i] = out_b[i];
    __syncthreads();

    // ---- Phase 3b: this slice writes channels [cbeg, cbeg+512), 2 tokens.
    float* op = out + (size_t)b * Cc * Tt + t0;
    #pragma unroll 4
    for (int c = cbeg; c < cbeg + CH; c++) {
        const u64* wp = reinterpret_cast<const u64*>(buf + c * 8);
        u64 w0 = wp[0], w1 = wp[1], w2 = wp[2], w3 = wp[3];
        u64 d0 = ffma2(q0p[0], w0, ffma2(q0p[1], w1,
                 ffma2(q0p[2], w2, fmul2(q0p[3], w3))));
        u64 d1 = ffma2(q1p[0], w0, ffma2(q1p[1], w1,
                 ffma2(q1p[2], w2, fmul2(q1p[3], w3))));
        float bcb = aux[c];
        float lo, hi;
        upk2(d0, lo, hi); float s0 = (lo + hi) + bcb;
        upk2(d1, lo, hi); float s1 = (lo + hi) + bcb;
        *reinterpret_cast<float2*>(op + (size_t)c * Tt) = make_float2(s0, s1);
    }

    if (slice == 0 && ids_out) {
        *reinterpret_cast<float2*>(ids_out + (size_t)b * Tt + t0) =
            make_float2((float)bi0, (float)bi1);
    }
}

extern "C" void kernel_launch(void* const* d_in, const int* in_sizes, int n_in,
                              void* d_out, int out_size) {
    const float* z     = (const float*)d_in[0];
    const float* in_w  = (const float*)d_in[1];
    const float* in_b  = (const float*)d_in[2];
    const float* cb    = (const float*)d_in[3];
    const float* out_w = (const float*)d_in[4];
    const float* out_b = (const float*)d_in[5];

    float* out = (float*)d_out;
    const long long out_elems = (long long)Bb * Cc * Tt;
    float* ids = (out_size > out_elems) ? out + out_elems : nullptr;

    dim3 grid(Bb * (Tt / TT));   // 256 blocks x 256 threads, 2 tokens/thread
    vq_fused<<<grid, NT>>>(z, in_w, in_b, cb, out_w, out_b, out, ids);
}

// round 10
// speedup vs baseline: 1.2203x; 1.0277x over previous
#include <cuda_runtime.h>
#include <float.h>

// _VQ_29609504538631 : fused VQ-VAE bottleneck
// R9: instruction-diet pass on R8.
//   - LDS.128 (ulonglong2) for all weight/codebook row fetches
//   - bias/half-norm folded into ffma2 accumulator init (pre-paired u64 smem)
//   - phase-2 processes codes in pairs: 2 independent dot chains, 1 cheap
//     pair-reduce (SETP+FMNMX+SEL), top-2 update once per 2 codes
// e computation bit-identical to R8 (chunk-64 fp32 + fp64 merge); fp64
// rescore of 4 candidates per token unchanged.

namespace {
constexpr int Bb = 8;
constexpr int Cc = 1024;
constexpr int Tt = 8192;
constexpr int Kk = 1024;
constexpr int Dd = 8;
constexpr int TT  = 256;              // tokens per block (128 pairs)
constexpr int NP  = 128;              // token-pairs per block
constexpr int SL  = 2;                // channel/code slices per token
constexpr int NT  = NP * SL;          // 256 threads
constexpr int CH  = Cc / SL;          // 512 channels per slice
constexpr int KH  = Kk / SL;          // 512 codes per slice
constexpr int CHUNK = 64;             // fp32 accumulation chunk (validated)
}

typedef unsigned long long u64;

__device__ __forceinline__ u64 pk2(float lo, float hi) {
    u64 r; asm("mov.b64 %0, {%1,%2};" : "=l"(r) : "f"(lo), "f"(hi)); return r;
}
__device__ __forceinline__ void upk2(u64 v, float& lo, float& hi) {
    asm("mov.b64 {%0,%1}, %2;" : "=f"(lo), "=f"(hi) : "l"(v));
}
__device__ __forceinline__ u64 ffma2(u64 a, u64 b, u64 c) {
    u64 r; asm("fma.rn.f32x2 %0, %1, %2, %3;" : "=l"(r) : "l"(a), "l"(b), "l"(c)); return r;
}

__global__ __launch_bounds__(NT, 2) void vq_fused(
    const float* __restrict__ z,
    const float* __restrict__ in_w,    // [D, C]
    const float* __restrict__ in_b,    // [D]
    const float* __restrict__ cb,      // [K, D]
    const float* __restrict__ out_w,   // [C, D]
    const float* __restrict__ out_b,   // [C]
    float* __restrict__ out,           // [B, C, T]
    float* __restrict__ ids_out)       // [B, T] (as float), may be null
{
    __shared__ __align__(16) float buf[Dd * Cc];    // 32 KB: in_w->cb->out_w
    __shared__ u64    aux2[Kk];                     // 8 KB: (-0.5||w||^2,0) / (out_b,0)
    __shared__ double exch[SL][NP][2][Dd];          // 32 KB fp64 partials
    __shared__ int    cand_i[SL][NP][2][2];         // 4 KB candidate ids
    __shared__ float  bias_in[Dd];

    const int tid   = threadIdx.x;
    const int slice = tid >> 7;           // 0/1
    const int pr    = tid & (NP - 1);     // pair index in block
    const int b     = blockIdx.x / (Tt / TT);
    const int t0    = (blockIdx.x % (Tt / TT)) * TT + 2 * pr;   // even

    // ---- Phase 0: stage in_w transposed -> buf[c*8+d]
    for (int i = tid; i < Dd * Cc; i += NT) {
        int d = i & 7, c = i >> 3;
        buf[i] = in_w[d * Cc + c];
    }
    if (tid < Dd) bias_in[tid] = in_b[tid];
    __syncthreads();

    // ---- Phase 1: partial e over this slice's 512 channels, 2 tokens packed.
    // Per-lane FMA chain bit-identical to R8/R2 scalar chain.
    double p0[Dd], p1[Dd];
    #pragma unroll
    for (int d = 0; d < Dd; d++) { p0[d] = 0.0; p1[d] = 0.0; }

    const float* zp = z + (size_t)b * Cc * Tt + t0;
    const int cbeg = slice * CH;
    for (int c0 = cbeg; c0 < cbeg + CH; c0 += CHUNK) {
        u64 a0[4], a1[4];
        #pragma unroll
        for (int j = 0; j < 4; j++) { a0[j] = 0ull; a1[j] = 0ull; }
        #pragma unroll 8
        for (int cc = 0; cc < CHUNK; cc++) {
            int c = c0 + cc;
            float2 v2 = __ldg(reinterpret_cast<const float2*>(zp + (size_t)c * Tt));
            u64 v0 = pk2(v2.x, v2.x);
            u64 v1 = pk2(v2.y, v2.y);
            const ulonglong2* wp = reinterpret_cast<const ulonglong2*>(buf + c * 8);
            ulonglong2 wA = wp[0];     // d0..d3 as two u64 lanesets
            ulonglong2 wB = wp[1];     // d4..d7
            a0[0] = ffma2(v0, wA.x, a0[0]);
            a0[1] = ffma2(v0, wA.y, a0[1]);
            a0[2] = ffma2(v0, wB.x, a0[2]);
            a0[3] = ffma2(v0, wB.y, a0[3]);
            a1[0] = ffma2(v1, wA.x, a1[0]);
            a1[1] = ffma2(v1, wA.y, a1[1]);
            a1[2] = ffma2(v1, wB.x, a1[2]);
            a1[3] = ffma2(v1, wB.y, a1[3]);
        }
        #pragma unroll
        for (int j = 0; j < 4; j++) {
            float lo, hi;
            upk2(a0[j], lo, hi); p0[2*j] += (double)lo; p0[2*j+1] += (double)hi;
            upk2(a1[j], lo, hi); p1[2*j] += (double)lo; p1[2*j+1] += (double)hi;
        }
    }
    #pragma unroll
    for (int d = 0; d < Dd; d++) {
        exch[slice][pr][0][d] = p0[d];
        exch[slice][pr][1][d] = p1[d];
    }
    __syncthreads();   // buf(in_w) reads done; partials published

    // merge partials in identical order on both slice threads
    float e0[Dd], e1[Dd];
    #pragma unroll
    for (int d = 0; d < Dd; d++) {
        e0[d] = (float)((exch[0][pr][0][d] + exch[1][pr][0][d]) + (double)bias_in[d]);
        e1[d] = (float)((exch[0][pr][1][d] + exch[1][pr][1][d]) + (double)bias_in[d]);
    }

    // ---- Phase 2a: stage codebook + pre-paired (-0.5||w||^2, 0)
    for (int k = tid; k < Kk; k += NT) {
        float4 c0 = __ldg(reinterpret_cast<const float4*>(cb + k * 8));
        float4 c1 = __ldg(reinterpret_cast<const float4*>(cb + k * 8) + 1);
        reinterpret_cast<float4*>(buf)[k * 2]     = c0;
        reinterpret_cast<float4*>(buf)[k * 2 + 1] = c1;
        double n = (double)c0.x*c0.x + (double)c0.y*c0.y
                 + (double)c0.z*c0.z + (double)c0.w*c0.w
                 + (double)c1.x*c1.x + (double)c1.y*c1.y
                 + (double)c1.z*c1.z + (double)c1.w*c1.w;
        aux2[k] = pk2(-(float)(0.5 * n), 0.0f);
    }
    __syncthreads();

    // ---- Phase 2b: scan this slice's 512 codes (in pairs) for both tokens.
    u64 ep0[4], ep1[4];
    #pragma unroll
    for (int j = 0; j < 4; j++) {
        ep0[j] = pk2(e0[2*j], e0[2*j+1]);
        ep1[j] = pk2(e1[2*j], e1[2*j+1]);
    }
    float b1t0 = -FLT_MAX, b2t0 = -FLT_MAX, b1t1 = -FLT_MAX, b2t1 = -FLT_MAX;
    int   i1t0 = slice*KH, i2t0 = slice*KH, i1t1 = slice*KH, i2t1 = slice*KH;
    const int kbeg = slice * KH;
    #pragma unroll 2
    for (int k = kbeg; k < kbeg + KH; k += 2) {
        const ulonglong2* wp = reinterpret_cast<const ulonglong2*>(buf + k * 8);
        ulonglong2 wa0 = wp[0], wa1 = wp[1];   // code k
        ulonglong2 wb0 = wp[2], wb1 = wp[3];   // code k+1
        u64 ia = aux2[k];
        u64 ib = aux2[k + 1];
        // token 0, codes k and k+1 (two independent chains)
        u64 da = ffma2(ep0[3], wa1.y, ffma2(ep0[2], wa1.x,
                 ffma2(ep0[1], wa0.y, ffma2(ep0[0], wa0.x, ia))));
        u64 db = ffma2(ep0[3], wb1.y, ffma2(ep0[2], wb1.x,
                 ffma2(ep0[1], wb0.y, ffma2(ep0[0], wb0.x, ib))));
        float lo, hi;
        upk2(da, lo, hi); float sa0 = lo + hi;
        upk2(db, lo, hi); float sb0 = lo + hi;
        // token 1
        da = ffma2(ep1[3], wa1.y, ffma2(ep1[2], wa1.x,
             ffma2(ep1[1], wa0.y, ffma2(ep1[0], wa0.x, ia))));
        db = ffma2(ep1[3], wb1.y, ffma2(ep1[2], wb1.x,
             ffma2(ep1[1], wb0.y, ffma2(ep1[0], wb0.x, ib))));
        upk2(da, lo, hi); float sa1 = lo + hi;
        upk2(db, lo, hi); float sb1 = lo + hi;
        // pair-reduce (ties -> lower k), then branchless top-2 update
        {
            bool pa = sa0 >= sb0;
            float sm = pa ? sa0 : sb0;
            int   km = pa ? k : k + 1;
            bool q2 = sm > b2t0;
            float c2 = q2 ? sm : b2t0;  int j2 = q2 ? km : i2t0;
            bool q1 = sm > b1t0;
            b2t0 = q1 ? b1t0 : c2;      i2t0 = q1 ? i1t0 : j2;
            b1t0 = q1 ? sm : b1t0;      i1t0 = q1 ? km : i1t0;
        }
        {
            bool pa = sa1 >= sb1;
            float sm = pa ? sa1 : sb1;
            int   km = pa ? k : k + 1;
            bool q2 = sm > b2t1;
            float c2 = q2 ? sm : b2t1;  int j2 = q2 ? km : i2t1;
            bool q1 = sm > b1t1;
            b2t1 = q1 ? b1t1 : c2;      i2t1 = q1 ? i1t1 : j2;
            b1t1 = q1 ? sm : b1t1;      i1t1 = q1 ? km : i1t1;
        }
    }
    cand_i[slice][pr][0][0] = i1t0;  cand_i[slice][pr][0][1] = i2t0;
    cand_i[slice][pr][1][0] = i1t1;  cand_i[slice][pr][1][1] = i2t1;
    __syncthreads();

    // ---- fp64 rescore of all 4 candidates per token; lowest index on ties.
    int bi0 = 0, bi1 = 0;
    #pragma unroll
    for (int tk = 0; tk < 2; tk++) {
        const float* ee = tk ? e1 : e0;
        double bscore = -DBL_MAX;
        int    bidx   = Kk;
        #pragma unroll
        for (int j = 0; j < 4; j++) {
            int kc = cand_i[j >> 1][pr][tk][j & 1];
            const float* w = buf + kc * 8;
            double dot = 0.0, nrm = 0.0;
            #pragma unroll
            for (int i = 0; i < Dd; i++) {
                double wi = (double)w[i];
                dot += (double)ee[i] * wi;
                nrm += wi * wi;
            }
            double sc = dot - 0.5 * nrm;
            if (sc > bscore || (sc == bscore && kc < bidx)) {
                bscore = sc; bidx = kc;
            }
        }
        if (tk) bi1 = bidx; else bi0 = bidx;
    }

    // grab winning codes (as d-pairs) before buf is overwritten
    u64 q0p[4], q1p[4];
    {
        const ulonglong2* w0 = reinterpret_cast<const ulonglong2*>(buf + bi0 * 8);
        const ulonglong2* w1 = reinterpret_cast<const ulonglong2*>(buf + bi1 * 8);
        ulonglong2 x0 = w0[0], x1 = w0[1], y0 = w1[0], y1 = w1[1];
        q0p[0] = x0.x; q0p[1] = x0.y; q0p[2] = x1.x; q0p[3] = x1.y;
        q1p[0] = y0.x; q1p[1] = y0.y; q1p[2] = y1.x; q1p[3] = y1.y;
    }
    __syncthreads();   // codebook reads done

    // ---- Phase 3a: stage out_w ([C,D] already c*8+d); aux2 <- (out_b, 0)
    for (int i = tid; i < Cc * Dd; i += NT) buf[i] = out_w[i];
    for (int i = tid; i < Cc; i += NT)      aux2[i] = pk2(out_b[i], 0.0f);
    __syncthreads();

    // ---- Phase 3b: this slice writes channels [cbeg, cbeg+512), 2 tokens.
    float* op = out + (size_t)b * Cc * Tt + t0;
    #pragma unroll 4
    for (int c = cbeg; c < cbeg + CH; c++) {
        const ulonglong2* wp = reinterpret_cast<const ulonglong2*>(buf + c * 8);
        ulonglong2 wA = wp[0], wB = wp[1];
        u64 ic = aux2[c];
        u64 d0 = ffma2(q0p[3], wB.y, ffma2(q0p[2], wB.x,
                 ffma2(q0p[1], wA.y, ffma2(q0p[0], wA.x, ic))));
        u64 d1 = ffma2(q1p[3], wB.y, ffma2(q1p[2], wB.x,
                 ffma2(q1p[1], wA.y, ffma2(q1p[0], wA.x, ic))));
        float lo, hi;
        upk2(d0, lo, hi); float s0 = lo + hi;
        upk2(d1, lo, hi); float s1 = lo + hi;
        *reinterpret_cast<float2*>(op + (size_t)c * Tt) = make_float2(s0, s1);
    }

    if (slice == 0 && ids_out) {
        *reinterpret_cast<float2*>(ids_out + (size_t)b * Tt + t0) =
            make_float2((float)bi0, (float)bi1);
    }
}

extern "C" void kernel_launch(void* const* d_in, const int* in_sizes, int n_in,
                              void* d_out, int out_size) {
    const float* z     = (const float*)d_in[0];
    const float* in_w  = (const float*)d_in[1];
    const float* in_b  = (const float*)d_in[2];
    const float* cb    = (const float*)d_in[3];
    const float* out_w = (const float*)d_in[4];
    const float* out_b = (const float*)d_in[5];

    float* out = (float*)d_out;
    const long long out_elems = (long long)Bb * Cc * Tt;
    float* ids = (out_size > out_elems) ? out + out_elems : nullptr;

    dim3 grid(Bb * (Tt / TT));   // 256 blocks x 256 threads, 2 tokens/thread
    vq_fused<<<grid, NT>>>(z, in_w, in_b, cb, out_w, out_b, out, ids);
}